// round 5
// baseline (speedup 1.0000x reference)
#include <cuda_runtime.h>
#include <math.h>
#include <stdint.h>

// Problem constants
#define Bc 2
#define Nn 2048
#define DIMc 1024
#define Hh 16
#define HDc 64
#define Pp 2
#define M_ROWS (Bc * Nn)        // 4096
#define THREE_DIM (3 * DIMc)    // 3072

// Scratch (no cudaMalloc allowed)
__device__ float g_qkv[M_ROWS * THREE_DIM];
__device__ float g_q[Bc * Hh * Nn * HDc];   // (b,h,n,d), tf32-rounded, q pre-scaled
__device__ float g_k[Bc * Hh * Nn * HDc];
__device__ float g_v[Bc * Hh * Nn * HDc];
__device__ float g_attn[M_ROWS * DIMc];     // (b*n, h*HD), tf32-rounded
__device__ float g_xr[M_ROWS * DIMc];       // tf32-rounded x
__device__ float g_wqkvr[DIMc * THREE_DIM]; // tf32-rounded w_qkv
__device__ float g_woutr[DIMc * DIMc];      // tf32-rounded w_out

// ---------------------------------------------------------------------------
// helpers
// ---------------------------------------------------------------------------
__device__ __forceinline__ uint32_t f2tf(float x) {
    uint32_t r;
    asm("cvt.rna.tf32.f32 %0, %1;" : "=r"(r) : "f"(x));
    return r;
}
__device__ __forceinline__ float f2tff(float x) { return __uint_as_float(f2tf(x)); }
__device__ __forceinline__ float ex2(float x) {
    float r;
    asm("ex2.approx.ftz.f32 %0, %1;" : "=f"(r) : "f"(x));
    return r;
}
__device__ __forceinline__ void mma_tf32(float d[4], const uint32_t a[4], const uint32_t b[2]) {
    asm volatile(
        "mma.sync.aligned.m16n8k8.row.col.f32.tf32.tf32.f32 "
        "{%0,%1,%2,%3}, {%4,%5,%6,%7}, {%8,%9}, {%0,%1,%2,%3};\n"
        : "+f"(d[0]), "+f"(d[1]), "+f"(d[2]), "+f"(d[3])
        : "r"(a[0]), "r"(a[1]), "r"(a[2]), "r"(a[3]), "r"(b[0]), "r"(b[1]));
}
__device__ __forceinline__ void cp16(uint32_t s, const void* g) {
    asm volatile("cp.async.ca.shared.global [%0], [%1], 16;\n" :: "r"(s), "l"(g));
}
#define CP_COMMIT() asm volatile("cp.async.commit_group;\n" ::: "memory")
#define CP_WAIT0()  asm volatile("cp.async.wait_group 0;\n" ::: "memory")
#define CP_WAIT1()  asm volatile("cp.async.wait_group 1;\n" ::: "memory")
__device__ __forceinline__ uint32_t s2u(const void* p) {
    return (uint32_t)__cvta_generic_to_shared(p);
}

// ---------------------------------------------------------------------------
// elementwise tf32-round copy
// ---------------------------------------------------------------------------
__global__ __launch_bounds__(256) void roundcopy(
    const float4* __restrict__ src, float4* __restrict__ dst, int n4)
{
    int i = blockIdx.x * blockDim.x + threadIdx.x;
    if (i < n4) {
        float4 v = src[i];
        v.x = f2tff(v.x); v.y = f2tff(v.y); v.z = f2tff(v.z); v.w = f2tff(v.w);
        dst[i] = v;
    }
}

// ---------------------------------------------------------------------------
// tf32 GEMM, cp.async double-buffered. 256 threads = 8 warps (2x4),
// CTA tile 128x128, warp tile 64x32, BK=16. Inputs pre-rounded to tf32.
// ---------------------------------------------------------------------------
#define APITCH 20
#define BPITCH 136

__global__ __launch_bounds__(256) void gemm_cp(
    const float* __restrict__ A, const float* __restrict__ B,
    float* __restrict__ C, int M, int N, int K,
    const float* __restrict__ bias)
{
    __shared__ float As[2][128 * APITCH];   // [m][k] pitch 20
    __shared__ float Bs[2][16 * BPITCH];    // [k][n] pitch 136

    int tid = threadIdx.x, lane = tid & 31, warp = tid >> 5;
    int wm = (warp >> 2) * 64, wn = (warp & 3) * 32;
    int rb = blockIdx.y * 128, cb = blockIdx.x * 128;

    int ar = tid >> 1, ac = (tid & 1) * 8;
    int bk = tid >> 4, bn = (tid & 15) * 8;

    uint32_t as_[2], bs_[2];
    as_[0] = s2u(&As[0][ar * APITCH + ac]);
    as_[1] = s2u(&As[1][ar * APITCH + ac]);
    bs_[0] = s2u(&Bs[0][bk * BPITCH + bn]);
    bs_[1] = s2u(&Bs[1][bk * BPITCH + bn]);

    const float* Ap = A + (size_t)(rb + ar) * K + ac;
    const float* Bp = B + (size_t)bk * N + cb + bn;

    // preload stage 0
    cp16(as_[0], Ap);       cp16(as_[0] + 16, Ap + 4);
    cp16(bs_[0], Bp);       cp16(bs_[0] + 16, Bp + 4);
    CP_COMMIT();

    float acc[4][4][4];
#pragma unroll
    for (int mt = 0; mt < 4; mt++)
#pragma unroll
        for (int nt = 0; nt < 4; nt++)
#pragma unroll
            for (int i = 0; i < 4; i++) acc[mt][nt][i] = 0.f;

    int nk = K / 16;
    for (int kt = 0; kt < nk; kt++) {
        if (kt + 1 < nk) {
            const float* Ap2 = Ap + (kt + 1) * 16;
            const float* Bp2 = Bp + (size_t)(kt + 1) * 16 * N;
            int s2 = (kt + 1) & 1;
            cp16(as_[s2], Ap2);       cp16(as_[s2] + 16, Ap2 + 4);
            cp16(bs_[s2], Bp2);       cp16(bs_[s2] + 16, Bp2 + 4);
            CP_COMMIT();
            CP_WAIT1();
        } else {
            CP_WAIT0();
        }
        __syncthreads();

        int s = kt & 1;
#pragma unroll
        for (int ks = 0; ks < 2; ks++) {
            int kb = ks * 8 + (lane & 3);
            uint32_t afr[4][4], bfr[4][2];
#pragma unroll
            for (int mt = 0; mt < 4; mt++) {
                int r0 = wm + mt * 16 + (lane >> 2);
                afr[mt][0] = __float_as_uint(As[s][r0 * APITCH + kb]);
                afr[mt][1] = __float_as_uint(As[s][(r0 + 8) * APITCH + kb]);
                afr[mt][2] = __float_as_uint(As[s][r0 * APITCH + kb + 4]);
                afr[mt][3] = __float_as_uint(As[s][(r0 + 8) * APITCH + kb + 4]);
            }
#pragma unroll
            for (int nt = 0; nt < 4; nt++) {
                int n0 = wn + nt * 8 + (lane >> 2);
                bfr[nt][0] = __float_as_uint(Bs[s][kb * BPITCH + n0]);
                bfr[nt][1] = __float_as_uint(Bs[s][(kb + 4) * BPITCH + n0]);
            }
#pragma unroll
            for (int mt = 0; mt < 4; mt++)
#pragma unroll
                for (int nt = 0; nt < 4; nt++)
                    mma_tf32(acc[mt][nt], afr[mt], bfr[nt]);
        }
        __syncthreads();
    }

#pragma unroll
    for (int mt = 0; mt < 4; mt++) {
        int r0 = rb + wm + mt * 16 + (lane >> 2);
#pragma unroll
        for (int nt = 0; nt < 4; nt++) {
            int c0 = cb + wn + nt * 8 + 2 * (lane & 3);
            float bx = 0.f, by = 0.f;
            if (bias) { bx = bias[c0]; by = bias[c0 + 1]; }
            float2 o0 = make_float2(acc[mt][nt][0] + bx, acc[mt][nt][1] + by);
            float2 o1 = make_float2(acc[mt][nt][2] + bx, acc[mt][nt][3] + by);
            *(float2*)&C[(size_t)r0 * N + c0] = o0;
            *(float2*)&C[(size_t)(r0 + 8) * N + c0] = o1;
        }
    }
}

// ---------------------------------------------------------------------------
// Axial RoPE + scatter to (b,h,n,d). Outputs tf32-rounded; q pre-scaled by
// 1/sqrt(HD) * log2(e) so flash works in exp2 domain with no per-elt math.
// ---------------------------------------------------------------------------
__global__ __launch_bounds__(256) void rope_scatter(
    const float* __restrict__ qkv, const float* __restrict__ pos,
    float* __restrict__ qo, float* __restrict__ ko, float* __restrict__ vo)
{
    const float SC = 0.125f * 1.44269504f;
    int t = threadIdx.x;
    for (int bn = blockIdx.x; bn < M_ROWS; bn += gridDim.x) {
        int b = bn / Nn, n = bn % Nn;
        __shared__ float cs[32], sn[32];
        if (t < 32) {
            int p = t >> 4, i = t & 15;
            float freq = expf(-(float)i * (9.210340371976184f / 16.f));
            float th = pos[(size_t)bn * Pp + p] * freq;
            float s, c;
            sincosf(th, &s, &c);
            cs[t] = c;
            sn[t] = s;
        }
        __syncthreads();
        const float* base = qkv + (size_t)bn * THREE_DIM;
        for (int idx = t; idx < Hh * 32; idx += 256) {
            int h = idx >> 5, d = idx & 31;
            float c = cs[d], s = sn[d];
            size_t off = ((size_t)(b * Hh + h) * Nn + n) * HDc;
            float x1 = base[h * HDc + d];
            float x2 = base[h * HDc + 32 + d];
            qo[off + d]      = f2tff((x1 * c - x2 * s) * SC);
            qo[off + 32 + d] = f2tff((x1 * s + x2 * c) * SC);
            x1 = base[DIMc + h * HDc + d];
            x2 = base[DIMc + h * HDc + 32 + d];
            ko[off + d]      = f2tff(x1 * c - x2 * s);
            ko[off + 32 + d] = f2tff(x1 * s + x2 * c);
            vo[off + d]      = f2tff(base[2 * DIMc + h * HDc + d]);
            vo[off + 32 + d] = f2tff(base[2 * DIMc + h * HDc + 32 + d]);
        }
        __syncthreads();
    }
}

// ---------------------------------------------------------------------------
// Flash attention v2-style: 128 threads = 4 warps, each owns 16 query rows
// of a 64-query tile (full softmax state in registers). 64-key tiles,
// cp.async double-buffered K/V, Q fragments register-resident.
// ---------------------------------------------------------------------------
#define FP 68
#define TILE_F (64 * FP)
#define FLASH_BYTES ((4 * TILE_F + TILE_F) * 4)   // K0,V0,K1,V1 + Ps

__global__ __launch_bounds__(128) void flash2(
    const float* __restrict__ Q, const float* __restrict__ K,
    const float* __restrict__ V, float* __restrict__ O)
{
    extern __shared__ float sm[];
    float* KT0 = sm;
    float* VT0 = sm + TILE_F;
    float* KT1 = sm + 2 * TILE_F;
    float* VT1 = sm + 3 * TILE_F;
    float* Ps  = sm + 4 * TILE_F;

    int tid = threadIdx.x, lane = tid & 31, warp = tid >> 5;
    int bh = blockIdx.y, qt = blockIdx.x;
    int b = bh >> 4, h = bh & 15;
    const float* Qb = Q + ((size_t)bh * Nn + qt * 64) * HDc;
    const float* Kb = K + (size_t)bh * Nn * HDc;
    const float* Vb = V + (size_t)bh * Nn * HDc;

    int r0 = warp * 16 + (lane >> 2);

    // Q fragments (register-resident for whole kernel)
    uint32_t qfr[8][4];
#pragma unroll
    for (int ks = 0; ks < 8; ks++) {
        int kb = ks * 8 + (lane & 3);
        qfr[ks][0] = __float_as_uint(Qb[(size_t)r0 * HDc + kb]);
        qfr[ks][1] = __float_as_uint(Qb[(size_t)(r0 + 8) * HDc + kb]);
        qfr[ks][2] = __float_as_uint(Qb[(size_t)r0 * HDc + kb + 4]);
        qfr[ks][3] = __float_as_uint(Qb[(size_t)(r0 + 8) * HDc + kb + 4]);
    }

    float accO[8][4];
#pragma unroll
    for (int nt = 0; nt < 8; nt++)
#pragma unroll
        for (int i = 0; i < 4; i++) accO[nt][i] = 0.f;
    float mA = -1e30f, mB = -1e30f, lA = 0.f, lB = 0.f;

    // cp.async loader mapping: thread -> row tid>>1, cols (tid&1)*32 .. +31
    int lr = tid >> 1, lc = (tid & 1) * 32;
    uint32_t ks0 = s2u(&KT0[lr * FP + lc]);
    uint32_t vs0 = s2u(&VT0[lr * FP + lc]);
    uint32_t ks1 = s2u(&KT1[lr * FP + lc]);
    uint32_t vs1 = s2u(&VT1[lr * FP + lc]);

    // preload tile 0
    {
        const float* kg = Kb + (size_t)lr * HDc + lc;
        const float* vg = Vb + (size_t)lr * HDc + lc;
#pragma unroll
        for (int j = 0; j < 8; j++) {
            cp16(ks0 + j * 16, kg + j * 4);
            cp16(vs0 + j * 16, vg + j * 4);
        }
        CP_COMMIT();
    }

    const int NT = Nn / 64;
    for (int kt = 0; kt < NT; kt++) {
        if (kt + 1 < NT) {
            const float* kg = Kb + ((size_t)(kt + 1) * 64 + lr) * HDc + lc;
            const float* vg = Vb + ((size_t)(kt + 1) * 64 + lr) * HDc + lc;
            uint32_t kd = ((kt + 1) & 1) ? ks1 : ks0;
            uint32_t vd = ((kt + 1) & 1) ? vs1 : vs0;
#pragma unroll
            for (int j = 0; j < 8; j++) {
                cp16(kd + j * 16, kg + j * 4);
                cp16(vd + j * 16, vg + j * 4);
            }
            CP_COMMIT();
            CP_WAIT1();
        } else {
            CP_WAIT0();
        }
        __syncthreads();

        const float* Ks = (kt & 1) ? KT1 : KT0;
        const float* Vs = (kt & 1) ? VT1 : VT0;

        // S = Q @ K^T  (warp: 16 q-rows x 64 keys)
        float s[8][4];
#pragma unroll
        for (int nt = 0; nt < 8; nt++)
#pragma unroll
            for (int i = 0; i < 4; i++) s[nt][i] = 0.f;
#pragma unroll
        for (int ks = 0; ks < 8; ks++) {
            int kb = ks * 8 + (lane & 3);
#pragma unroll
            for (int nt = 0; nt < 8; nt++) {
                int n0 = nt * 8 + (lane >> 2);
                uint32_t bfr[2];
                bfr[0] = __float_as_uint(Ks[n0 * FP + kb]);
                bfr[1] = __float_as_uint(Ks[n0 * FP + kb + 4]);
                mma_tf32(s[nt], qfr[ks], bfr);
            }
        }

        // row max (register + shfl within 4-lane row groups)
        float ma = -1e30f, mb = -1e30f;
#pragma unroll
        for (int nt = 0; nt < 8; nt++) {
            ma = fmaxf(ma, fmaxf(s[nt][0], s[nt][1]));
            mb = fmaxf(mb, fmaxf(s[nt][2], s[nt][3]));
        }
        ma = fmaxf(ma, __shfl_xor_sync(0xffffffffu, ma, 1));
        ma = fmaxf(ma, __shfl_xor_sync(0xffffffffu, ma, 2));
        mb = fmaxf(mb, __shfl_xor_sync(0xffffffffu, mb, 1));
        mb = fmaxf(mb, __shfl_xor_sync(0xffffffffu, mb, 2));

        float mnA = fmaxf(mA, ma), mnB = fmaxf(mB, mb);
        float fA = ex2(mA - mnA), fB = ex2(mB - mnB);

        // exponentiate, partial sums, stage P to smem (tf32)
        float sa = 0.f, sb = 0.f;
#pragma unroll
        for (int nt = 0; nt < 8; nt++) {
            float p0 = ex2(s[nt][0] - mnA);
            float p1 = ex2(s[nt][1] - mnA);
            float p2 = ex2(s[nt][2] - mnB);
            float p3 = ex2(s[nt][3] - mnB);
            sa += p0 + p1;
            sb += p2 + p3;
            int c0 = nt * 8 + 2 * (lane & 3);
            *(float2*)&Ps[r0 * FP + c0]       = make_float2(f2tff(p0), f2tff(p1));
            *(float2*)&Ps[(r0 + 8) * FP + c0] = make_float2(f2tff(p2), f2tff(p3));
        }
        sa += __shfl_xor_sync(0xffffffffu, sa, 1);
        sa += __shfl_xor_sync(0xffffffffu, sa, 2);
        sb += __shfl_xor_sync(0xffffffffu, sb, 1);
        sb += __shfl_xor_sync(0xffffffffu, sb, 2);
        lA = lA * fA + sa;
        lB = lB * fB + sb;
        mA = mnA;
        mB = mnB;

        // rescale O accumulators
#pragma unroll
        for (int nt = 0; nt < 8; nt++) {
            accO[nt][0] *= fA;
            accO[nt][1] *= fA;
            accO[nt][2] *= fB;
            accO[nt][3] *= fB;
        }
        __syncwarp();

        // O += P @ V
#pragma unroll
        for (int ks = 0; ks < 8; ks++) {
            int kb = ks * 8 + (lane & 3);
            uint32_t afr[4];
            afr[0] = __float_as_uint(Ps[r0 * FP + kb]);
            afr[1] = __float_as_uint(Ps[(r0 + 8) * FP + kb]);
            afr[2] = __float_as_uint(Ps[r0 * FP + kb + 4]);
            afr[3] = __float_as_uint(Ps[(r0 + 8) * FP + kb + 4]);
#pragma unroll
            for (int nt = 0; nt < 8; nt++) {
                int n0 = nt * 8 + (lane >> 2);
                uint32_t bfr[2];
                bfr[0] = __float_as_uint(Vs[kb * FP + n0]);
                bfr[1] = __float_as_uint(Vs[(kb + 4) * FP + n0]);
                mma_tf32(accO[nt], afr, bfr);
            }
        }
        __syncthreads();   // all reads of this K/V buffer done before reuse
    }

    // epilogue: normalize, round to tf32 (input of out-proj), store
    float iA = 1.f / lA, iB = 1.f / lB;
    size_t rowA = ((size_t)(b * Nn + qt * 64 + r0)) * DIMc + h * HDc;
    size_t rowB = ((size_t)(b * Nn + qt * 64 + r0 + 8)) * DIMc + h * HDc;
#pragma unroll
    for (int nt = 0; nt < 8; nt++) {
        int c0 = nt * 8 + 2 * (lane & 3);
        *(float2*)&O[rowA + c0] = make_float2(f2tff(accO[nt][0] * iA), f2tff(accO[nt][1] * iA));
        *(float2*)&O[rowB + c0] = make_float2(f2tff(accO[nt][2] * iB), f2tff(accO[nt][3] * iB));
    }
}

// ---------------------------------------------------------------------------
extern "C" void kernel_launch(void* const* d_in, const int* in_sizes, int n_in,
                              void* d_out, int out_size)
{
    (void)in_sizes; (void)n_in; (void)out_size;
    const float* x     = (const float*)d_in[0];
    const float* pos   = (const float*)d_in[1];
    const float* w_qkv = (const float*)d_in[2];
    const float* w_out = (const float*)d_in[3];
    const float* b_out = (const float*)d_in[4];
    float* out = (float*)d_out;

    float *qkv, *q, *k, *v, *attn, *xr, *wqkvr, *woutr;
    cudaGetSymbolAddress((void**)&qkv,   g_qkv);
    cudaGetSymbolAddress((void**)&q,     g_q);
    cudaGetSymbolAddress((void**)&k,     g_k);
    cudaGetSymbolAddress((void**)&v,     g_v);
    cudaGetSymbolAddress((void**)&attn,  g_attn);
    cudaGetSymbolAddress((void**)&xr,    g_xr);
    cudaGetSymbolAddress((void**)&wqkvr, g_wqkvr);
    cudaGetSymbolAddress((void**)&woutr, g_woutr);

    cudaFuncSetAttribute(flash2,
                         cudaFuncAttributeMaxDynamicSharedMemorySize,
                         FLASH_BYTES);

    // 0) pre-round inputs to tf32
    {
        int n4x = M_ROWS * DIMc / 4;
        int n4w = DIMc * THREE_DIM / 4;
        int n4o = DIMc * DIMc / 4;
        roundcopy<<<(n4x + 255) / 256, 256>>>((const float4*)x, (float4*)xr, n4x);
        roundcopy<<<(n4w + 255) / 256, 256>>>((const float4*)w_qkv, (float4*)wqkvr, n4w);
        roundcopy<<<(n4o + 255) / 256, 256>>>((const float4*)w_out, (float4*)woutr, n4o);
    }
    // 1) QKV projection
    {
        dim3 grid(THREE_DIM / 128, M_ROWS / 128);
        gemm_cp<<<grid, 256>>>(xr, wqkvr, qkv, M_ROWS, THREE_DIM, DIMc, nullptr);
    }
    // 2) RoPE + scatter (tf32-rounded outputs, q pre-scaled)
    rope_scatter<<<512, 256>>>(qkv, pos, q, k, v);
    // 3) Flash attention
    {
        dim3 grid(Nn / 64, Bc * Hh);
        flash2<<<grid, 128, FLASH_BYTES>>>(q, k, v, attn);
    }
    // 4) Output projection + bias
    {
        dim3 grid(DIMc / 128, M_ROWS / 128);
        gemm_cp<<<grid, 256>>>(attn, woutr, out, M_ROWS, DIMc, DIMc, b_out);
    }
}

// round 6
// speedup vs baseline: 1.1891x; 1.1891x over previous
#include <cuda_runtime.h>
#include <math.h>
#include <stdint.h>

// Problem constants
#define Bc 2
#define Nn 2048
#define DIMc 1024
#define Hh 16
#define HDc 64
#define Pp 2
#define M_ROWS (Bc * Nn)        // 4096
#define THREE_DIM (3 * DIMc)    // 3072

// Scratch (no cudaMalloc allowed)
__device__ float g_qkv[M_ROWS * THREE_DIM];
__device__ float g_q[Bc * Hh * Nn * HDc];   // (b,h,n,d)
__device__ float g_k[Bc * Hh * Nn * HDc];
__device__ float g_v[Bc * Hh * Nn * HDc];
__device__ float g_attn[M_ROWS * DIMc];     // (b*n, h*HD), tf32-rounded by flash epi
__device__ float g_xr[M_ROWS * DIMc];       // tf32-rounded x
__device__ float g_wqkvr[DIMc * THREE_DIM]; // tf32-rounded w_qkv
__device__ float g_woutr[DIMc * DIMc];      // tf32-rounded w_out

// ---------------------------------------------------------------------------
// helpers
// ---------------------------------------------------------------------------
__device__ __forceinline__ uint32_t f2tf(float x) {
    uint32_t r;
    asm("cvt.rna.tf32.f32 %0, %1;" : "=r"(r) : "f"(x));
    return r;
}
__device__ __forceinline__ float f2tff(float x) { return __uint_as_float(f2tf(x)); }
__device__ __forceinline__ float ex2(float x) {
    float r;
    asm("ex2.approx.ftz.f32 %0, %1;" : "=f"(r) : "f"(x));
    return r;
}
__device__ __forceinline__ void mma_tf32(float d[4], const uint32_t a[4], const uint32_t b[2]) {
    asm volatile(
        "mma.sync.aligned.m16n8k8.row.col.f32.tf32.tf32.f32 "
        "{%0,%1,%2,%3}, {%4,%5,%6,%7}, {%8,%9}, {%0,%1,%2,%3};\n"
        : "+f"(d[0]), "+f"(d[1]), "+f"(d[2]), "+f"(d[3])
        : "r"(a[0]), "r"(a[1]), "r"(a[2]), "r"(a[3]), "r"(b[0]), "r"(b[1]));
}
__device__ __forceinline__ void cp16(uint32_t s, const void* g) {
    asm volatile("cp.async.ca.shared.global [%0], [%1], 16;\n" :: "r"(s), "l"(g));
}
#define CP_COMMIT() asm volatile("cp.async.commit_group;\n" ::: "memory")
#define CP_WAIT0()  asm volatile("cp.async.wait_group 0;\n" ::: "memory")
#define CP_WAIT1()  asm volatile("cp.async.wait_group 1;\n" ::: "memory")
__device__ __forceinline__ uint32_t s2u(const void* p) {
    return (uint32_t)__cvta_generic_to_shared(p);
}

// ---------------------------------------------------------------------------
// elementwise tf32-round copy
// ---------------------------------------------------------------------------
__global__ __launch_bounds__(256) void roundcopy(
    const float4* __restrict__ src, float4* __restrict__ dst, int n4)
{
    int i = blockIdx.x * blockDim.x + threadIdx.x;
    if (i < n4) {
        float4 v = src[i];
        v.x = f2tff(v.x); v.y = f2tff(v.y); v.z = f2tff(v.z); v.w = f2tff(v.w);
        dst[i] = v;
    }
}

// ---------------------------------------------------------------------------
// tf32 GEMM, cp.async double-buffered. R4 compute structure: 128 threads =
// 4 warps (2x2), CTA tile 128x128, warp tile 64x64, BK=16.
// Inputs must be pre-rounded to tf32.
// ---------------------------------------------------------------------------
#define GAP 20    // As pitch (floats)
#define GBP 136   // Bs pitch (floats)

__global__ __launch_bounds__(128) void gemm_cp2(
    const float* __restrict__ A, const float* __restrict__ B,
    float* __restrict__ C, int M, int N, int K,
    const float* __restrict__ bias)
{
    __shared__ float As[2][128 * GAP];   // [m][k], BK=16
    __shared__ float Bs[2][16 * GBP];    // [k][n]

    int tid = threadIdx.x, lane = tid & 31, warp = tid >> 5;
    int wm = (warp >> 1) * 64, wn = (warp & 1) * 64;
    int rb = blockIdx.y * 128, cb = blockIdx.x * 128;

    // cp.async loader mapping
    // A: thread -> row tid (128 rows), 16 k-floats = 4x cp16
    // B: thread -> row tid>>3 (16 rows), cols (tid&7)*16 .. +15 = 4x cp16
    int brow = tid >> 3, bcol = (tid & 7) * 16;

    uint32_t as_[2], bs_[2];
    as_[0] = s2u(&As[0][tid * GAP]);
    as_[1] = s2u(&As[1][tid * GAP]);
    bs_[0] = s2u(&Bs[0][brow * GBP + bcol]);
    bs_[1] = s2u(&Bs[1][brow * GBP + bcol]);

    const float* Ap = A + (size_t)(rb + tid) * K;
    const float* Bp = B + (size_t)brow * N + cb + bcol;

    // preload stage 0
#pragma unroll
    for (int j = 0; j < 4; j++) {
        cp16(as_[0] + j * 16, Ap + j * 4);
        cp16(bs_[0] + j * 16, Bp + j * 4);
    }
    CP_COMMIT();

    float acc[4][8][4];
#pragma unroll
    for (int mt = 0; mt < 4; mt++)
#pragma unroll
        for (int nt = 0; nt < 8; nt++)
#pragma unroll
            for (int i = 0; i < 4; i++) acc[mt][nt][i] = 0.f;

    int nk = K / 16;
    for (int kt = 0; kt < nk; kt++) {
        if (kt + 1 < nk) {
            int s2 = (kt + 1) & 1;
            const float* Ap2 = Ap + (kt + 1) * 16;
            const float* Bp2 = Bp + (size_t)(kt + 1) * 16 * N;
#pragma unroll
            for (int j = 0; j < 4; j++) {
                cp16(as_[s2] + j * 16, Ap2 + j * 4);
                cp16(bs_[s2] + j * 16, Bp2 + j * 4);
            }
            CP_COMMIT();
            CP_WAIT1();
        } else {
            CP_WAIT0();
        }
        __syncthreads();

        int s = kt & 1;
#pragma unroll
        for (int ks = 0; ks < 2; ks++) {
            int kb = ks * 8 + (lane & 3);
            uint32_t afr[4][4], bfr[8][2];
#pragma unroll
            for (int mt = 0; mt < 4; mt++) {
                int r0 = wm + mt * 16 + (lane >> 2);
                afr[mt][0] = __float_as_uint(As[s][r0 * GAP + kb]);
                afr[mt][1] = __float_as_uint(As[s][(r0 + 8) * GAP + kb]);
                afr[mt][2] = __float_as_uint(As[s][r0 * GAP + kb + 4]);
                afr[mt][3] = __float_as_uint(As[s][(r0 + 8) * GAP + kb + 4]);
            }
#pragma unroll
            for (int nt = 0; nt < 8; nt++) {
                int n0 = wn + nt * 8 + (lane >> 2);
                bfr[nt][0] = __float_as_uint(Bs[s][kb * GBP + n0]);
                bfr[nt][1] = __float_as_uint(Bs[s][(kb + 4) * GBP + n0]);
            }
#pragma unroll
            for (int mt = 0; mt < 4; mt++)
#pragma unroll
                for (int nt = 0; nt < 8; nt++)
                    mma_tf32(acc[mt][nt], afr[mt], bfr[nt]);
        }
        __syncthreads();
    }

    // epilogue
#pragma unroll
    for (int mt = 0; mt < 4; mt++) {
        int r0 = rb + wm + mt * 16 + (lane >> 2);
#pragma unroll
        for (int nt = 0; nt < 8; nt++) {
            int c0 = cb + wn + nt * 8 + 2 * (lane & 3);
            float bx = 0.f, by = 0.f;
            if (bias) { bx = bias[c0]; by = bias[c0 + 1]; }
            float2 o0 = make_float2(acc[mt][nt][0] + bx, acc[mt][nt][1] + by);
            float2 o1 = make_float2(acc[mt][nt][2] + bx, acc[mt][nt][3] + by);
            *(float2*)&C[(size_t)r0 * N + c0] = o0;
            *(float2*)&C[(size_t)(r0 + 8) * N + c0] = o1;
        }
    }
}

// ---------------------------------------------------------------------------
// Axial RoPE + scatter to (b,h,n,d)  (R4 version, unchanged)
// ---------------------------------------------------------------------------
__global__ __launch_bounds__(256) void rope_scatter(
    const float* __restrict__ qkv, const float* __restrict__ pos,
    float* __restrict__ qo, float* __restrict__ ko, float* __restrict__ vo)
{
    int t = threadIdx.x;
    for (int bn = blockIdx.x; bn < M_ROWS; bn += gridDim.x) {
        int b = bn / Nn, n = bn % Nn;
        __shared__ float cs[32], sn[32];
        if (t < 32) {
            int p = t >> 4, i = t & 15;
            float freq = expf(-(float)i * (9.210340371976184f / 16.f));
            float th = pos[(size_t)bn * Pp + p] * freq;
            float s, c;
            sincosf(th, &s, &c);
            cs[t] = c;
            sn[t] = s;
        }
        __syncthreads();
        const float* base = qkv + (size_t)bn * THREE_DIM;
        for (int idx = t; idx < Hh * 32; idx += 256) {
            int h = idx >> 5, d = idx & 31;
            float c = cs[d], s = sn[d];
            size_t off = ((size_t)(b * Hh + h) * Nn + n) * HDc;
            float x1 = base[h * HDc + d];
            float x2 = base[h * HDc + 32 + d];
            qo[off + d]      = x1 * c - x2 * s;
            qo[off + 32 + d] = x1 * s + x2 * c;
            x1 = base[DIMc + h * HDc + d];
            x2 = base[DIMc + h * HDc + 32 + d];
            ko[off + d]      = x1 * c - x2 * s;
            ko[off + 32 + d] = x1 * s + x2 * c;
            vo[off + d]      = base[2 * DIMc + h * HDc + d];
            vo[off + 32 + d] = base[2 * DIMc + h * HDc + 32 + d];
        }
        __syncthreads();
    }
}

// ---------------------------------------------------------------------------
// Flash attention (R4 version, unchanged except tf32-round of output so the
// out-projection can consume it without in-kernel conversion).
// ---------------------------------------------------------------------------
#define FP 68
#define FLASH_SMEM_FLOATS (4 * 64 * FP + 64 + 64 + 128 + 128)
#define FLASH_SMEM_BYTES (FLASH_SMEM_FLOATS * 4)

__global__ __launch_bounds__(128) void flash_tf32(
    const float* __restrict__ Q, const float* __restrict__ K,
    const float* __restrict__ V, float* __restrict__ O)
{
    extern __shared__ float smf[];
    float* Qs = smf;
    float* Ks = Qs + 64 * FP;
    float* Vs = Ks + 64 * FP;
    float* Ps = Vs + 64 * FP;
    float* mrow = Ps + 64 * FP;   // 64
    float* lrow = mrow + 64;      // 64
    float* rmax = lrow + 64;      // 2*64
    float* rsum = rmax + 128;     // 2*64

    int tid = threadIdx.x, lane = tid & 31, warp = tid >> 5;
    int wm = (warp >> 1) * 32, wn = (warp & 1) * 32;
    int bh = blockIdx.y;
    int b = bh >> 4, h = bh & 15;
    int qt = blockIdx.x;

    const float* Qb = Q + ((size_t)bh * Nn + qt * 64) * HDc;
    const float* Kb = K + (size_t)bh * Nn * HDc;
    const float* Vb = V + (size_t)bh * Nn * HDc;

    const float SC = 0.125f * 1.44269504f;  // 1/sqrt(64) * log2(e)

    // load Q tile scaled+converted
    {
        int r = tid >> 4, c = (tid & 15) * 4;
#pragma unroll
        for (int p = 0; p < 8; p++) {
            int rr = r + 8 * p;
            float4 q4 = *(const float4*)&Qb[(size_t)rr * HDc + c];
            float4 t;
            t.x = __uint_as_float(f2tf(q4.x * SC));
            t.y = __uint_as_float(f2tf(q4.y * SC));
            t.z = __uint_as_float(f2tf(q4.z * SC));
            t.w = __uint_as_float(f2tf(q4.w * SC));
            *(float4*)&Qs[rr * FP + c] = t;
        }
    }
    if (tid < 64) { mrow[tid] = -1e30f; lrow[tid] = 0.f; }

    float accO[2][4][4];
#pragma unroll
    for (int mt = 0; mt < 2; mt++)
#pragma unroll
        for (int nt = 0; nt < 4; nt++)
#pragma unroll
            for (int i = 0; i < 4; i++) accO[mt][nt][i] = 0.f;

    __syncthreads();

    for (int kt = 0; kt < Nn / 64; kt++) {
        // load K,V tiles (converted to tf32)
        {
            int r = tid >> 4, c = (tid & 15) * 4;
#pragma unroll
            for (int p = 0; p < 8; p++) {
                int rr = r + 8 * p;
                float4 k4 = *(const float4*)&Kb[((size_t)(kt * 64 + rr)) * HDc + c];
                float4 v4 = *(const float4*)&Vb[((size_t)(kt * 64 + rr)) * HDc + c];
                float4 tk, tv;
                tk.x = __uint_as_float(f2tf(k4.x));
                tk.y = __uint_as_float(f2tf(k4.y));
                tk.z = __uint_as_float(f2tf(k4.z));
                tk.w = __uint_as_float(f2tf(k4.w));
                tv.x = __uint_as_float(f2tf(v4.x));
                tv.y = __uint_as_float(f2tf(v4.y));
                tv.z = __uint_as_float(f2tf(v4.z));
                tv.w = __uint_as_float(f2tf(v4.w));
                *(float4*)&Ks[rr * FP + c] = tk;
                *(float4*)&Vs[rr * FP + c] = tv;
            }
        }
        __syncthreads();   // (1) tiles ready

        // S = Qs @ Ks^T (warp tile 32x32)
        float s[2][4][4];
#pragma unroll
        for (int mt = 0; mt < 2; mt++)
#pragma unroll
            for (int nt = 0; nt < 4; nt++)
#pragma unroll
                for (int i = 0; i < 4; i++) s[mt][nt][i] = 0.f;
#pragma unroll
        for (int ks = 0; ks < 8; ks++) {
            int kb = ks * 8 + (lane & 3);
            uint32_t afr[2][4], bfr[4][2];
#pragma unroll
            for (int mt = 0; mt < 2; mt++) {
                int r0 = wm + mt * 16 + (lane >> 2);
                afr[mt][0] = __float_as_uint(Qs[r0 * FP + kb]);
                afr[mt][1] = __float_as_uint(Qs[(r0 + 8) * FP + kb]);
                afr[mt][2] = __float_as_uint(Qs[r0 * FP + kb + 4]);
                afr[mt][3] = __float_as_uint(Qs[(r0 + 8) * FP + kb + 4]);
            }
#pragma unroll
            for (int nt = 0; nt < 4; nt++) {
                int n0 = wn + nt * 8 + (lane >> 2);
                bfr[nt][0] = __float_as_uint(Ks[n0 * FP + kb]);
                bfr[nt][1] = __float_as_uint(Ks[n0 * FP + kb + 4]);
            }
#pragma unroll
            for (int mt = 0; mt < 2; mt++)
#pragma unroll
                for (int nt = 0; nt < 4; nt++)
                    mma_tf32(s[mt][nt], afr[mt], bfr[nt]);
        }

        // row max (per-thread -> bfly over lane%4 group -> smem)
        float mxa[2], mxb[2];
#pragma unroll
        for (int mt = 0; mt < 2; mt++) {
            float ma = -1e30f, mb = -1e30f;
#pragma unroll
            for (int nt = 0; nt < 4; nt++) {
                ma = fmaxf(ma, fmaxf(s[mt][nt][0], s[mt][nt][1]));
                mb = fmaxf(mb, fmaxf(s[mt][nt][2], s[mt][nt][3]));
            }
            ma = fmaxf(ma, __shfl_xor_sync(0xffffffffu, ma, 1));
            ma = fmaxf(ma, __shfl_xor_sync(0xffffffffu, ma, 2));
            mb = fmaxf(mb, __shfl_xor_sync(0xffffffffu, mb, 1));
            mb = fmaxf(mb, __shfl_xor_sync(0xffffffffu, mb, 2));
            mxa[mt] = ma; mxb[mt] = mb;
        }
        if ((lane & 3) == 0) {
#pragma unroll
            for (int mt = 0; mt < 2; mt++) {
                int rA = wm + mt * 16 + (lane >> 2);
                rmax[(warp & 1) * 64 + rA] = mxa[mt];
                rmax[(warp & 1) * 64 + rA + 8] = mxb[mt];
            }
        }
        __syncthreads();   // (2) rmax ready

        // m_new, rescale O, exponentiate, partial sums, store P
#pragma unroll
        for (int mt = 0; mt < 2; mt++) {
            int rA = wm + mt * 16 + (lane >> 2);
            int rB = rA + 8;
            float moA = mrow[rA];
            float moB = mrow[rB];
            float mnA = fmaxf(moA, fmaxf(rmax[rA], rmax[64 + rA]));
            float mnB = fmaxf(moB, fmaxf(rmax[rB], rmax[64 + rB]));
            float fA = ex2(moA - mnA);
            float fB = ex2(moB - mnB);
            float sa = 0.f, sb = 0.f;
#pragma unroll
            for (int nt = 0; nt < 4; nt++) {
                float p0 = ex2(s[mt][nt][0] - mnA);
                float p1 = ex2(s[mt][nt][1] - mnA);
                float p2 = ex2(s[mt][nt][2] - mnB);
                float p3 = ex2(s[mt][nt][3] - mnB);
                sa += p0 + p1;
                sb += p2 + p3;
                accO[mt][nt][0] *= fA;
                accO[mt][nt][1] *= fA;
                accO[mt][nt][2] *= fB;
                accO[mt][nt][3] *= fB;
                int base = rA * FP + wn + nt * 8 + 2 * (lane & 3);
                Ps[base]     = __uint_as_float(f2tf(p0));
                Ps[base + 1] = __uint_as_float(f2tf(p1));
                Ps[rB * FP + wn + nt * 8 + 2 * (lane & 3)]     = __uint_as_float(f2tf(p2));
                Ps[rB * FP + wn + nt * 8 + 2 * (lane & 3) + 1] = __uint_as_float(f2tf(p3));
            }
            sa += __shfl_xor_sync(0xffffffffu, sa, 1);
            sa += __shfl_xor_sync(0xffffffffu, sa, 2);
            sb += __shfl_xor_sync(0xffffffffu, sb, 1);
            sb += __shfl_xor_sync(0xffffffffu, sb, 2);
            if ((lane & 3) == 0) {
                rsum[(warp & 1) * 64 + rA] = sa;
                rsum[(warp & 1) * 64 + rB] = sb;
            }
        }
        __syncthreads();   // (3) P + rsum ready

        // update running stats (one thread per row)
        if (tid < 64) {
            int r = tid;
            float mo = mrow[r];
            float mn = fmaxf(mo, fmaxf(rmax[r], rmax[64 + r]));
            lrow[r] = lrow[r] * ex2(mo - mn) + rsum[r] + rsum[64 + r];
            mrow[r] = mn;
        }

        // O += P @ V
#pragma unroll
        for (int ks = 0; ks < 8; ks++) {
            int kb = ks * 8 + (lane & 3);
            uint32_t afr[2][4], bfr[4][2];
#pragma unroll
            for (int mt = 0; mt < 2; mt++) {
                int r0 = wm + mt * 16 + (lane >> 2);
                afr[mt][0] = __float_as_uint(Ps[r0 * FP + kb]);
                afr[mt][1] = __float_as_uint(Ps[(r0 + 8) * FP + kb]);
                afr[mt][2] = __float_as_uint(Ps[r0 * FP + kb + 4]);
                afr[mt][3] = __float_as_uint(Ps[(r0 + 8) * FP + kb + 4]);
            }
#pragma unroll
            for (int nt = 0; nt < 4; nt++) {
                int n0 = wn + nt * 8 + (lane >> 2);
                bfr[nt][0] = __float_as_uint(Vs[kb * FP + n0]);
                bfr[nt][1] = __float_as_uint(Vs[(kb + 4) * FP + n0]);
            }
#pragma unroll
            for (int mt = 0; mt < 2; mt++)
#pragma unroll
                for (int nt = 0; nt < 4; nt++)
                    mma_tf32(accO[mt][nt], afr[mt], bfr[nt]);
        }
        __syncthreads();   // (4) safe to overwrite tiles / stats visible
    }

    // epilogue: normalize, round to tf32 (input of out-proj), store
#pragma unroll
    for (int mt = 0; mt < 2; mt++) {
        int rA = wm + mt * 16 + (lane >> 2);
        int rB = rA + 8;
        float ia = 1.f / lrow[rA];
        float ib = 1.f / lrow[rB];
        size_t rowA = ((size_t)(b * Nn + qt * 64 + rA)) * DIMc + h * HDc;
        size_t rowB = ((size_t)(b * Nn + qt * 64 + rB)) * DIMc + h * HDc;
#pragma unroll
        for (int nt = 0; nt < 4; nt++) {
            int c0 = wn + nt * 8 + 2 * (lane & 3);
            float2 oA = make_float2(f2tff(accO[mt][nt][0] * ia), f2tff(accO[mt][nt][1] * ia));
            float2 oB = make_float2(f2tff(accO[mt][nt][2] * ib), f2tff(accO[mt][nt][3] * ib));
            *(float2*)&O[rowA + c0] = oA;
            *(float2*)&O[rowB + c0] = oB;
        }
    }
}

// ---------------------------------------------------------------------------
extern "C" void kernel_launch(void* const* d_in, const int* in_sizes, int n_in,
                              void* d_out, int out_size)
{
    (void)in_sizes; (void)n_in; (void)out_size;
    const float* x     = (const float*)d_in[0];
    const float* pos   = (const float*)d_in[1];
    const float* w_qkv = (const float*)d_in[2];
    const float* w_out = (const float*)d_in[3];
    const float* b_out = (const float*)d_in[4];
    float* out = (float*)d_out;

    float *qkv, *q, *k, *v, *attn, *xr, *wqkvr, *woutr;
    cudaGetSymbolAddress((void**)&qkv,   g_qkv);
    cudaGetSymbolAddress((void**)&q,     g_q);
    cudaGetSymbolAddress((void**)&k,     g_k);
    cudaGetSymbolAddress((void**)&v,     g_v);
    cudaGetSymbolAddress((void**)&attn,  g_attn);
    cudaGetSymbolAddress((void**)&xr,    g_xr);
    cudaGetSymbolAddress((void**)&wqkvr, g_wqkvr);
    cudaGetSymbolAddress((void**)&woutr, g_woutr);

    cudaFuncSetAttribute(flash_tf32,
                         cudaFuncAttributeMaxDynamicSharedMemorySize,
                         FLASH_SMEM_BYTES);

    // 0) pre-round GEMM inputs to tf32 (RN — matches R4's in-kernel rounding)
    {
        int n4x = M_ROWS * DIMc / 4;
        int n4w = DIMc * THREE_DIM / 4;
        int n4o = DIMc * DIMc / 4;
        roundcopy<<<(n4x + 255) / 256, 256>>>((const float4*)x, (float4*)xr, n4x);
        roundcopy<<<(n4w + 255) / 256, 256>>>((const float4*)w_qkv, (float4*)wqkvr, n4w);
        roundcopy<<<(n4o + 255) / 256, 256>>>((const float4*)w_out, (float4*)woutr, n4o);
    }
    // 1) QKV projection
    {
        dim3 grid(THREE_DIM / 128, M_ROWS / 128);
        gemm_cp2<<<grid, 128>>>(xr, wqkvr, qkv, M_ROWS, THREE_DIM, DIMc, nullptr);
    }
    // 2) RoPE + scatter
    rope_scatter<<<512, 256>>>(qkv, pos, q, k, v);
    // 3) Flash attention
    {
        dim3 grid(Nn / 64, Bc * Hh);
        flash_tf32<<<grid, 128, FLASH_SMEM_BYTES>>>(q, k, v, attn);
    }
    // 4) Output projection + bias
    {
        dim3 grid(DIMc / 128, M_ROWS / 128);
        gemm_cp2<<<grid, 128>>>(attn, woutr, out, M_ROWS, DIMc, DIMc, b_out);
    }
}

// round 7
// speedup vs baseline: 2.3037x; 1.9374x over previous
#include <cuda_runtime.h>
#include <cuda_fp16.h>
#include <math.h>
#include <stdint.h>

// Problem constants
#define Bc 2
#define Nn 2048
#define DIMc 1024
#define Hh 16
#define HDc 64
#define Pp 2
#define M_ROWS (Bc * Nn)        // 4096
#define THREE_DIM (3 * DIMc)    // 3072

// Scratch (no cudaMalloc allowed)
__device__ float  g_qkv[M_ROWS * THREE_DIM];       // f32 qkv projection output
__device__ __half g_xh[M_ROWS * DIMc];             // fp16 x
__device__ __half g_wqkvh[DIMc * THREE_DIM];       // fp16 w_qkv
__device__ __half g_wouth[DIMc * DIMc];            // fp16 w_out
__device__ __half g_q[Bc * Hh * Nn * HDc];         // (b,h,n,d), q pre-scaled
__device__ __half g_k[Bc * Hh * Nn * HDc];
__device__ __half g_v[Bc * Hh * Nn * HDc];
__device__ __half g_attn[M_ROWS * DIMc];           // (b*n, h*HD)

// ---------------------------------------------------------------------------
// helpers
// ---------------------------------------------------------------------------
__device__ __forceinline__ float ex2(float x) {
    float r;
    asm("ex2.approx.ftz.f32 %0, %1;" : "=f"(r) : "f"(x));
    return r;
}
__device__ __forceinline__ void mma_f16(float d[4], const uint32_t a[4], const uint32_t b[2]) {
    asm volatile(
        "mma.sync.aligned.m16n8k16.row.col.f32.f16.f16.f32 "
        "{%0,%1,%2,%3}, {%4,%5,%6,%7}, {%8,%9}, {%0,%1,%2,%3};\n"
        : "+f"(d[0]), "+f"(d[1]), "+f"(d[2]), "+f"(d[3])
        : "r"(a[0]), "r"(a[1]), "r"(a[2]), "r"(a[3]), "r"(b[0]), "r"(b[1]));
}
__device__ __forceinline__ void ldm_x4(uint32_t r[4], uint32_t addr) {
    asm volatile("ldmatrix.sync.aligned.m8n8.x4.shared.b16 {%0,%1,%2,%3}, [%4];"
                 : "=r"(r[0]), "=r"(r[1]), "=r"(r[2]), "=r"(r[3]) : "r"(addr));
}
__device__ __forceinline__ void ldm_x2(uint32_t r[2], uint32_t addr) {
    asm volatile("ldmatrix.sync.aligned.m8n8.x2.shared.b16 {%0,%1}, [%2];"
                 : "=r"(r[0]), "=r"(r[1]) : "r"(addr));
}
__device__ __forceinline__ void ldm_x2t(uint32_t r[2], uint32_t addr) {
    asm volatile("ldmatrix.sync.aligned.m8n8.x2.trans.shared.b16 {%0,%1}, [%2];"
                 : "=r"(r[0]), "=r"(r[1]) : "r"(addr));
}
__device__ __forceinline__ uint32_t s2u(const void* p) {
    return (uint32_t)__cvta_generic_to_shared(p);
}

// ---------------------------------------------------------------------------
// f32 -> f16 convert (vectorized)
// ---------------------------------------------------------------------------
__global__ __launch_bounds__(256) void tohalf(
    const float4* __restrict__ src, uint2* __restrict__ dst, int n4)
{
    int i = blockIdx.x * blockDim.x + threadIdx.x;
    if (i < n4) {
        float4 v = src[i];
        __half2 h0 = __floats2half2_rn(v.x, v.y);
        __half2 h1 = __floats2half2_rn(v.z, v.w);
        uint2 o;
        o.x = *reinterpret_cast<uint32_t*>(&h0);
        o.y = *reinterpret_cast<uint32_t*>(&h1);
        dst[i] = o;
    }
}

// ---------------------------------------------------------------------------
// fp16 tensor-core GEMM: C[M,N](f32) = A[M,K](f16) @ B[K,N](f16) (+bias f32)
// 128 threads = 4 warps (2x2), CTA tile 128x128, warp tile 64x64, BK=32.
// R4-proven sync register-staged double buffer.
// ---------------------------------------------------------------------------
#define AP 40     // As pitch (halfs): 32 + 8
#define BP 136    // Bs pitch (halfs): 128 + 8

__global__ __launch_bounds__(128) void gemm_f16(
    const __half* __restrict__ A, const __half* __restrict__ B,
    float* __restrict__ C, int M, int N, int K,
    const float* __restrict__ bias)
{
    __shared__ __half As[2][128 * AP];   // [m][k]
    __shared__ __half Bs[2][32 * BP];    // [k][n]

    int tid = threadIdx.x, lane = tid & 31, warp = tid >> 5;
    int wm = (warp >> 1) * 64, wn = (warp & 1) * 64;
    int rb = blockIdx.y * 128, cb = blockIdx.x * 128;

    // loaders: A row tid (32 halfs = 4x uint4); B row tid>>2, cols (tid&3)*32
    int br = tid >> 2, bc = (tid & 3) * 32;
    const __half* Ap = A + (size_t)(rb + tid) * K;
    const __half* Bp = B + (size_t)br * N + cb + bc;

    uint4 ast[4], bst[4];
#pragma unroll
    for (int j = 0; j < 4; j++) {
        ast[j] = *(const uint4*)(Ap + j * 8);
        bst[j] = *(const uint4*)(Bp + j * 8);
    }
#pragma unroll
    for (int j = 0; j < 4; j++) {
        *(uint4*)&As[0][tid * AP + j * 8] = ast[j];
        *(uint4*)&Bs[0][br * BP + bc + j * 8] = bst[j];
    }
    __syncthreads();

    float acc[4][8][4];
#pragma unroll
    for (int mt = 0; mt < 4; mt++)
#pragma unroll
        for (int nt = 0; nt < 8; nt++)
#pragma unroll
            for (int i = 0; i < 4; i++) acc[mt][nt][i] = 0.f;

    int nk = K / 32;
    for (int kt = 0; kt < nk; kt++) {
        if (kt + 1 < nk) {
            const __half* Ap2 = Ap + (kt + 1) * 32;
            const __half* Bp2 = Bp + (size_t)(kt + 1) * 32 * N;
#pragma unroll
            for (int j = 0; j < 4; j++) {
                ast[j] = *(const uint4*)(Ap2 + j * 8);
                bst[j] = *(const uint4*)(Bp2 + j * 8);
            }
        }
        int s = kt & 1;
        uint32_t asb = s2u(&As[s][0]);
        uint32_t bsb = s2u(&Bs[s][0]);
#pragma unroll
        for (int ks = 0; ks < 2; ks++) {
            uint32_t afr[4][4], bfr[8][2];
#pragma unroll
            for (int mt = 0; mt < 4; mt++) {
                int row = wm + mt * 16 + (lane & 15);
                int col = ks * 16 + ((lane >> 4) << 3);
                ldm_x4(afr[mt], asb + (row * AP + col) * 2);
            }
#pragma unroll
            for (int nt = 0; nt < 8; nt++) {
                int row = ks * 16 + (lane & 15);
                int col = wn + nt * 8;
                ldm_x2t(bfr[nt], bsb + (row * BP + col) * 2);
            }
#pragma unroll
            for (int mt = 0; mt < 4; mt++)
#pragma unroll
                for (int nt = 0; nt < 8; nt++)
                    mma_f16(acc[mt][nt], afr[mt], bfr[nt]);
        }
        __syncthreads();
        if (kt + 1 < nk) {
            int s2 = (kt + 1) & 1;
#pragma unroll
            for (int j = 0; j < 4; j++) {
                *(uint4*)&As[s2][tid * AP + j * 8] = ast[j];
                *(uint4*)&Bs[s2][br * BP + bc + j * 8] = bst[j];
            }
            __syncthreads();
        }
    }

    // epilogue (f32)
#pragma unroll
    for (int mt = 0; mt < 4; mt++) {
        int r0 = rb + wm + mt * 16 + (lane >> 2);
#pragma unroll
        for (int nt = 0; nt < 8; nt++) {
            int c0 = cb + wn + nt * 8 + 2 * (lane & 3);
            float bx = 0.f, by = 0.f;
            if (bias) { bx = bias[c0]; by = bias[c0 + 1]; }
            float2 o0 = make_float2(acc[mt][nt][0] + bx, acc[mt][nt][1] + by);
            float2 o1 = make_float2(acc[mt][nt][2] + bx, acc[mt][nt][3] + by);
            *(float2*)&C[(size_t)r0 * N + c0] = o0;
            *(float2*)&C[(size_t)(r0 + 8) * N + c0] = o1;
        }
    }
}

// ---------------------------------------------------------------------------
// Axial RoPE + scatter to (b,h,n,d), fp16 outputs; q pre-scaled by
// 1/sqrt(HD)*log2(e) for exp2-domain softmax.
// ---------------------------------------------------------------------------
__global__ __launch_bounds__(256) void rope_scatter(
    const float* __restrict__ qkv, const float* __restrict__ pos,
    __half* __restrict__ qo, __half* __restrict__ ko, __half* __restrict__ vo)
{
    const float SC = 0.125f * 1.44269504f;
    int t = threadIdx.x;
    for (int bn = blockIdx.x; bn < M_ROWS; bn += gridDim.x) {
        int b = bn / Nn, n = bn % Nn;
        __shared__ float cs[32], sn[32];
        if (t < 32) {
            int p = t >> 4, i = t & 15;
            float freq = expf(-(float)i * (9.210340371976184f / 16.f));
            float th = pos[(size_t)bn * Pp + p] * freq;
            float s, c;
            sincosf(th, &s, &c);
            cs[t] = c;
            sn[t] = s;
        }
        __syncthreads();
        const float* base = qkv + (size_t)bn * THREE_DIM;
        for (int idx = t; idx < Hh * 32; idx += 256) {
            int h = idx >> 5, d = idx & 31;
            float c = cs[d], s = sn[d];
            size_t off = ((size_t)(b * Hh + h) * Nn + n) * HDc;
            float x1 = base[h * HDc + d];
            float x2 = base[h * HDc + 32 + d];
            qo[off + d]      = __float2half_rn((x1 * c - x2 * s) * SC);
            qo[off + 32 + d] = __float2half_rn((x1 * s + x2 * c) * SC);
            x1 = base[DIMc + h * HDc + d];
            x2 = base[DIMc + h * HDc + 32 + d];
            ko[off + d]      = __float2half_rn(x1 * c - x2 * s);
            ko[off + 32 + d] = __float2half_rn(x1 * s + x2 * c);
            vo[off + d]      = __float2half_rn(base[2 * DIMc + h * HDc + d]);
            vo[off + 32 + d] = __float2half_rn(base[2 * DIMc + h * HDc + 32 + d]);
        }
        __syncthreads();
    }
}

// ---------------------------------------------------------------------------
// Flash attention, fp16 mma (m16n8k16). 128 threads = 4 warps in 2x2 over
// a 64q x 64k tile (R4 structure). Q fragments hoisted to registers; Ps
// aliases Qs. Online softmax in exp2 domain (scale pre-folded into q).
// ---------------------------------------------------------------------------
#define QP 72   // half pitch: 64 + 8

__global__ __launch_bounds__(128) void flash_f16(
    const __half* __restrict__ Q, const __half* __restrict__ K,
    const __half* __restrict__ V, __half* __restrict__ O)
{
    __shared__ __half Qs[64 * QP];     // reused as Ps after Q frag hoist
    __shared__ __half Ks[64 * QP];
    __shared__ __half Vs[64 * QP];
    __shared__ float mrow[64], lrow[64], rmax[128], rsum[128];

    int tid = threadIdx.x, lane = tid & 31, warp = tid >> 5;
    int wm = (warp >> 1) * 32, wn = (warp & 1) * 32;
    int bh = blockIdx.y, qt = blockIdx.x;
    int b = bh >> 4, h = bh & 15;

    const __half* Qb = Q + ((size_t)bh * Nn + qt * 64) * HDc;
    const __half* Kb = K + (size_t)bh * Nn * HDc;
    const __half* Vb = V + (size_t)bh * Nn * HDc;

    // stage Q tile (64x64 halfs): thread -> row tid>>1, cols (tid&1)*32
    int lr = tid >> 1, lc = (tid & 1) * 32;
    {
        const __half* qg = Qb + (size_t)lr * HDc + lc;
#pragma unroll
        for (int j = 0; j < 4; j++)
            *(uint4*)&Qs[lr * QP + lc + j * 8] = *(const uint4*)(qg + j * 8);
    }
    if (tid < 64) { mrow[tid] = -1e30f; lrow[tid] = 0.f; }
    __syncthreads();

    // hoist Q fragments: qfr[ks][mt][4], ks over d (4 x k16), mt 2 x 16 rows
    uint32_t qfr[4][2][4];
    {
        uint32_t qsb = s2u(&Qs[0]);
#pragma unroll
        for (int ks = 0; ks < 4; ks++)
#pragma unroll
            for (int mt = 0; mt < 2; mt++) {
                int row = wm + mt * 16 + (lane & 15);
                int col = ks * 16 + ((lane >> 4) << 3);
                ldm_x4(qfr[ks][mt], qsb + (row * QP + col) * 2);
            }
    }
    __half* Ps = Qs;   // alias: Qs no longer needed

    float accO[2][4][4];
#pragma unroll
    for (int mt = 0; mt < 2; mt++)
#pragma unroll
        for (int nt = 0; nt < 4; nt++)
#pragma unroll
            for (int i = 0; i < 4; i++) accO[mt][nt][i] = 0.f;

    uint32_t ksb = s2u(&Ks[0]);
    uint32_t vsb = s2u(&Vs[0]);
    uint32_t psb = s2u(&Ps[0]);

    for (int kt = 0; kt < Nn / 64; kt++) {
        // load K,V tiles (pure fp16 copies)
        {
            const __half* kg = Kb + ((size_t)(kt * 64 + lr)) * HDc + lc;
            const __half* vg = Vb + ((size_t)(kt * 64 + lr)) * HDc + lc;
#pragma unroll
            for (int j = 0; j < 4; j++) {
                *(uint4*)&Ks[lr * QP + lc + j * 8] = *(const uint4*)(kg + j * 8);
                *(uint4*)&Vs[lr * QP + lc + j * 8] = *(const uint4*)(vg + j * 8);
            }
        }
        __syncthreads();   // (1) tiles ready; prev Ps fully consumed

        // S = Q @ K^T (warp tile 32x32). B frags from Ks rows=key (non-trans).
        float s[2][4][4];
#pragma unroll
        for (int mt = 0; mt < 2; mt++)
#pragma unroll
            for (int nt = 0; nt < 4; nt++)
#pragma unroll
                for (int i = 0; i < 4; i++) s[mt][nt][i] = 0.f;
#pragma unroll
        for (int ks = 0; ks < 4; ks++) {
#pragma unroll
            for (int nt = 0; nt < 4; nt++) {
                int row = wn + nt * 8 + (lane & 7);
                int col = ks * 16 + ((lane >> 3) & 1) * 8;
                uint32_t bfr[2];
                ldm_x2(bfr, ksb + (row * QP + col) * 2);
#pragma unroll
                for (int mt = 0; mt < 2; mt++)
                    mma_f16(s[mt][nt], qfr[ks][mt], bfr);
            }
        }

        // row max
        float mxa[2], mxb[2];
#pragma unroll
        for (int mt = 0; mt < 2; mt++) {
            float ma = -1e30f, mb = -1e30f;
#pragma unroll
            for (int nt = 0; nt < 4; nt++) {
                ma = fmaxf(ma, fmaxf(s[mt][nt][0], s[mt][nt][1]));
                mb = fmaxf(mb, fmaxf(s[mt][nt][2], s[mt][nt][3]));
            }
            ma = fmaxf(ma, __shfl_xor_sync(0xffffffffu, ma, 1));
            ma = fmaxf(ma, __shfl_xor_sync(0xffffffffu, ma, 2));
            mb = fmaxf(mb, __shfl_xor_sync(0xffffffffu, mb, 1));
            mb = fmaxf(mb, __shfl_xor_sync(0xffffffffu, mb, 2));
            mxa[mt] = ma; mxb[mt] = mb;
        }
        if ((lane & 3) == 0) {
#pragma unroll
            for (int mt = 0; mt < 2; mt++) {
                int rA = wm + mt * 16 + (lane >> 2);
                rmax[(warp & 1) * 64 + rA] = mxa[mt];
                rmax[(warp & 1) * 64 + rA + 8] = mxb[mt];
            }
        }
        __syncthreads();   // (2) rmax ready

        // exponentiate, rescale accO, partial sums, store P (fp16)
#pragma unroll
        for (int mt = 0; mt < 2; mt++) {
            int rA = wm + mt * 16 + (lane >> 2);
            int rB = rA + 8;
            float moA = mrow[rA];
            float moB = mrow[rB];
            float mnA = fmaxf(moA, fmaxf(rmax[rA], rmax[64 + rA]));
            float mnB = fmaxf(moB, fmaxf(rmax[rB], rmax[64 + rB]));
            float fA = ex2(moA - mnA);
            float fB = ex2(moB - mnB);
            float sa = 0.f, sb = 0.f;
#pragma unroll
            for (int nt = 0; nt < 4; nt++) {
                float p0 = ex2(s[mt][nt][0] - mnA);
                float p1 = ex2(s[mt][nt][1] - mnA);
                float p2 = ex2(s[mt][nt][2] - mnB);
                float p3 = ex2(s[mt][nt][3] - mnB);
                sa += p0 + p1;
                sb += p2 + p3;
                accO[mt][nt][0] *= fA;
                accO[mt][nt][1] *= fA;
                accO[mt][nt][2] *= fB;
                accO[mt][nt][3] *= fB;
                int c0 = wn + nt * 8 + 2 * (lane & 3);
                *(__half2*)&Ps[rA * QP + c0] = __floats2half2_rn(p0, p1);
                *(__half2*)&Ps[rB * QP + c0] = __floats2half2_rn(p2, p3);
            }
            sa += __shfl_xor_sync(0xffffffffu, sa, 1);
            sa += __shfl_xor_sync(0xffffffffu, sa, 2);
            sb += __shfl_xor_sync(0xffffffffu, sb, 1);
            sb += __shfl_xor_sync(0xffffffffu, sb, 2);
            if ((lane & 3) == 0) {
                rsum[(warp & 1) * 64 + rA] = sa;
                rsum[(warp & 1) * 64 + rB] = sb;
            }
        }
        __syncthreads();   // (3) P + rsum ready

        if (tid < 64) {
            int r = tid;
            float mo = mrow[r];
            float mn = fmaxf(mo, fmaxf(rmax[r], rmax[64 + r]));
            lrow[r] = lrow[r] * ex2(mo - mn) + rsum[r] + rsum[64 + r];
            mrow[r] = mn;
        }

        // O += P @ V. A frags from Ps rows=q; B frags from Vs via trans.
#pragma unroll
        for (int ks = 0; ks < 4; ks++) {
            uint32_t afr[2][4];
#pragma unroll
            for (int mt = 0; mt < 2; mt++) {
                int row = wm + mt * 16 + (lane & 15);
                int col = ks * 16 + ((lane >> 4) << 3);
                ldm_x4(afr[mt], psb + (row * QP + col) * 2);
            }
#pragma unroll
            for (int nt = 0; nt < 4; nt++) {
                int row = ks * 16 + (lane & 15);
                int col = wn + nt * 8;
                uint32_t bfr[2];
                ldm_x2t(bfr, vsb + (row * QP + col) * 2);
#pragma unroll
                for (int mt = 0; mt < 2; mt++)
                    mma_f16(accO[mt][nt], afr[mt], bfr);
            }
        }
        __syncthreads();   // (4) safe to overwrite K/V/Ps next iter
    }

    // epilogue: normalize, store fp16 to (b*n, h*HD)
#pragma unroll
    for (int mt = 0; mt < 2; mt++) {
        int rA = wm + mt * 16 + (lane >> 2);
        int rB = rA + 8;
        float ia = 1.f / lrow[rA];
        float ib = 1.f / lrow[rB];
        size_t rowA = ((size_t)(b * Nn + qt * 64 + rA)) * DIMc + h * HDc;
        size_t rowB = ((size_t)(b * Nn + qt * 64 + rB)) * DIMc + h * HDc;
#pragma unroll
        for (int nt = 0; nt < 4; nt++) {
            int c0 = wn + nt * 8 + 2 * (lane & 3);
            *(__half2*)&O[rowA + c0] = __floats2half2_rn(accO[mt][nt][0] * ia, accO[mt][nt][1] * ia);
            *(__half2*)&O[rowB + c0] = __floats2half2_rn(accO[mt][nt][2] * ib, accO[mt][nt][3] * ib);
        }
    }
}

// ---------------------------------------------------------------------------
extern "C" void kernel_launch(void* const* d_in, const int* in_sizes, int n_in,
                              void* d_out, int out_size)
{
    (void)in_sizes; (void)n_in; (void)out_size;
    const float* x     = (const float*)d_in[0];
    const float* pos   = (const float*)d_in[1];
    const float* w_qkv = (const float*)d_in[2];
    const float* w_out = (const float*)d_in[3];
    const float* b_out = (const float*)d_in[4];
    float* out = (float*)d_out;

    float* qkv;
    __half *xh, *wqkvh, *wouth, *q, *k, *v, *attn;
    cudaGetSymbolAddress((void**)&qkv,   g_qkv);
    cudaGetSymbolAddress((void**)&xh,    g_xh);
    cudaGetSymbolAddress((void**)&wqkvh, g_wqkvh);
    cudaGetSymbolAddress((void**)&wouth, g_wouth);
    cudaGetSymbolAddress((void**)&q,     g_q);
    cudaGetSymbolAddress((void**)&k,     g_k);
    cudaGetSymbolAddress((void**)&v,     g_v);
    cudaGetSymbolAddress((void**)&attn,  g_attn);

    // 0) convert inputs to fp16
    {
        int n4x = M_ROWS * DIMc / 4;
        int n4w = DIMc * THREE_DIM / 4;
        int n4o = DIMc * DIMc / 4;
        tohalf<<<(n4x + 255) / 256, 256>>>((const float4*)x, (uint2*)xh, n4x);
        tohalf<<<(n4w + 255) / 256, 256>>>((const float4*)w_qkv, (uint2*)wqkvh, n4w);
        tohalf<<<(n4o + 255) / 256, 256>>>((const float4*)w_out, (uint2*)wouth, n4o);
    }
    // 1) QKV projection (fp16 in, f32 out)
    {
        dim3 grid(THREE_DIM / 128, M_ROWS / 128);
        gemm_f16<<<grid, 128>>>(xh, wqkvh, qkv, M_ROWS, THREE_DIM, DIMc, nullptr);
    }
    // 2) RoPE + scatter (fp16 outputs, q pre-scaled)
    rope_scatter<<<512, 256>>>(qkv, pos, q, k, v);
    // 3) Flash attention (fp16)
    {
        dim3 grid(Nn / 64, Bc * Hh);
        flash_f16<<<grid, 128>>>(q, k, v, attn);
    }
    // 4) Output projection + bias
    {
        dim3 grid(DIMc / 128, M_ROWS / 128);
        gemm_f16<<<grid, 128>>>(attn, wouth, out, M_ROWS, DIMc, DIMc, b_out);
    }
}